// round 2
// baseline (speedup 1.0000x reference)
#include <cuda_runtime.h>
#include <cstdint>

#define NN 100000
#define EMAX 1600000
#define EPS 1e-5f

// ---- scratch (static __device__ globals; no allocation at runtime) ----
__device__ __align__(16) float g_bufA[(size_t)NN * 128];
__device__ __align__(16) float g_bufB[(size_t)NN * 128];
__device__ __align__(16) float g_bufC[(size_t)NN * 128];
__device__ float g_dinv[NN];
__device__ float g_norm[EMAX];
__device__ int   g_deg[NN];
__device__ int   g_src[EMAX];
__device__ int   g_dst[EMAX];
__device__ int   g_is64;

// ---------------------------------------------------------------------
// Detect whether edge_index is int64 or int32 (JAX without x64 silently
// downgrades jnp.int64 to int32). Under the int64 interpretation, valid
// indices must all be in [0, N); int32 data read as int64 packs two
// indices per word -> values >= 2^32 (unless hi word is 0, vanishingly
// unlikely across 1024 samples of uniform [0,100000)).
__global__ void detect_dtype_kernel(const void* ei_raw, int E, int n_nodes) {
    if (threadIdx.x == 0) g_is64 = 1;
    __syncthreads();
    const long long* e64 = (const long long*)ei_raw;
    int cnt = (2 * E < 1024) ? 2 * E : 1024;
    for (int i = threadIdx.x; i < cnt; i += blockDim.x) {
        long long v = e64[i];
        if (v < 0 || v >= n_nodes) atomicExch(&g_is64, 0);
    }
}

__global__ void zero_deg_kernel(int n) {
    int i = blockIdx.x * blockDim.x + threadIdx.x;
    if (i < n) g_deg[i] = 0;
}

__global__ void prep_edges_kernel(const void* ei_raw, int E) {
    int e = blockIdx.x * blockDim.x + threadIdx.x;
    if (e >= E) return;
    int s, d;
    if (g_is64) {
        const long long* ei = (const long long*)ei_raw;
        s = (int)ei[e];
        d = (int)ei[(size_t)E + e];
    } else {
        const int* ei = (const int*)ei_raw;
        s = ei[e];
        d = ei[(size_t)E + e];
    }
    g_src[e] = s;
    g_dst[e] = d;
    atomicAdd(&g_deg[d], 1);
}

__global__ void dinv_kernel(int n) {
    int i = blockIdx.x * blockDim.x + threadIdx.x;
    if (i < n) g_dinv[i] = rsqrtf((float)g_deg[i] + 1.0f);
}

__global__ void norm_kernel(int E) {
    int e = blockIdx.x * blockDim.x + threadIdx.x;
    if (e < E) g_norm[e] = g_dinv[g_src[e]] * g_dinv[g_dst[e]];
}

// ---- GEMM: C[N,Fo] = H[N,Fi] @ W[Fi,Fo], W staged in shared ----------
template <int Fi, int Fo, int NPT>
__global__ void gemm_kernel(const float* __restrict__ H,
                            const float* __restrict__ W,
                            float* __restrict__ C, int N) {
    constexpr int NR = 256 / Fo;          // node rows handled concurrently
    __shared__ float Ws[Fi * Fo];
    for (int i = threadIdx.x; i < Fi * Fo; i += 256) Ws[i] = W[i];
    __syncthreads();

    int fo = threadIdx.x % Fo;
    int nr = threadIdx.x / Fo;
    int n0 = blockIdx.x * (NR * NPT) + nr * NPT;

    float acc[NPT];
#pragma unroll
    for (int r = 0; r < NPT; r++) acc[r] = 0.0f;

#pragma unroll 4
    for (int k = 0; k < Fi; k++) {
        float w = Ws[k * Fo + fo];
#pragma unroll
        for (int r = 0; r < NPT; r++) {
            int n = n0 + r;
            if (n < N) acc[r] += H[(size_t)n * Fi + k] * w;
        }
    }
#pragma unroll
    for (int r = 0; r < NPT; r++) {
        int n = n0 + r;
        if (n < N) C[(size_t)n * Fo + fo] = acc[r];
    }
}

// ---- agg init: self-loop term + bias (avoids separate zeroing) -------
template <int Fo>
__global__ void self_init_kernel(const float* __restrict__ xw,
                                 const float* __restrict__ b,
                                 float* __restrict__ agg, int N) {
    int i = blockIdx.x * blockDim.x + threadIdx.x;
    if (i >= N * Fo) return;
    int n = i / Fo;
    int f = i % Fo;
    float di = g_dinv[n];
    agg[i] = xw[i] * di * di + b[f];
}

// ---- edge scatter: agg[dst] += xw[src] * norm, vectorized red.v4 -----
template <int LOGF4>
__global__ void edge_scatter_kernel(const float* __restrict__ xw,
                                    float* __restrict__ agg, int E) {
    constexpr int F4 = 1 << LOGF4;  // float4 chunks per row
    long long tid = (long long)blockIdx.x * blockDim.x + threadIdx.x;
    if (tid >= ((long long)E << LOGF4)) return;
    int e = (int)(tid >> LOGF4);
    int c = (int)(tid & (F4 - 1));
    int s = g_src[e];
    int d = g_dst[e];
    float nrm = g_norm[e];
    const float4* xw4 = reinterpret_cast<const float4*>(xw);
    float4 v = __ldg(&xw4[(size_t)s * F4 + c]);
    float* out = agg + ((size_t)d * F4 + c) * 4;
    asm volatile("red.global.add.v4.f32 [%0], {%1, %2, %3, %4};"
                 :: "l"(out), "f"(v.x * nrm), "f"(v.y * nrm),
                    "f"(v.z * nrm), "f"(v.w * nrm)
                 : "memory");
}

// ---- fused LayerNorm + ELU, one warp per node ------------------------
template <int Fo>
__global__ void ln_elu_kernel(const float* __restrict__ in,
                              const float* __restrict__ g,
                              const float* __restrict__ be,
                              float* __restrict__ out, int N) {
    constexpr int VPL = Fo / 32;
    int warp = (int)((blockIdx.x * blockDim.x + threadIdx.x) >> 5);
    int lane = threadIdx.x & 31;
    if (warp >= N) return;
    float v[VPL];
    float sum = 0.0f, sq = 0.0f;
#pragma unroll
    for (int i = 0; i < VPL; i++) {
        v[i] = in[(size_t)warp * Fo + lane + i * 32];
        sum += v[i];
        sq += v[i] * v[i];
    }
#pragma unroll
    for (int o = 16; o; o >>= 1) {
        sum += __shfl_xor_sync(0xffffffffu, sum, o);
        sq  += __shfl_xor_sync(0xffffffffu, sq, o);
    }
    float mean = sum * (1.0f / Fo);
    float var  = sq * (1.0f / Fo) - mean * mean;
    float inv  = rsqrtf(var + EPS);
#pragma unroll
    for (int i = 0; i < VPL; i++) {
        int f = lane + i * 32;
        float y = (v[i] - mean) * inv * g[f] + be[f];
        out[(size_t)warp * Fo + f] = (y > 0.0f) ? y : expm1f(y);
    }
}

// ---- fused head: lin(64->32) + LN + ELU + lin(32->32), thread/node ---
__global__ void head_kernel(const float* __restrict__ h,
                            const float* __restrict__ lw1,
                            const float* __restrict__ lb1,
                            const float* __restrict__ g4,
                            const float* __restrict__ be4,
                            const float* __restrict__ lw2,
                            const float* __restrict__ lb2,
                            float* __restrict__ out, int N) {
    __shared__ float s_w1[64 * 32];
    __shared__ float s_w2[32 * 32];
    __shared__ float s_b1[32], s_g4[32], s_be4[32], s_b2[32];
    for (int i = threadIdx.x; i < 64 * 32; i += blockDim.x) s_w1[i] = lw1[i];
    for (int i = threadIdx.x; i < 32 * 32; i += blockDim.x) s_w2[i] = lw2[i];
    if (threadIdx.x < 32) {
        s_b1[threadIdx.x]  = lb1[threadIdx.x];
        s_g4[threadIdx.x]  = g4[threadIdx.x];
        s_be4[threadIdx.x] = be4[threadIdx.x];
        s_b2[threadIdx.x]  = lb2[threadIdx.x];
    }
    __syncthreads();

    int n = blockIdx.x * blockDim.x + threadIdx.x;
    if (n >= N) return;

    float hv[64];
#pragma unroll
    for (int k = 0; k < 64; k++) hv[k] = h[(size_t)n * 64 + k];

    float t[32];
    float sum = 0.0f;
#pragma unroll
    for (int j = 0; j < 32; j++) {
        float acc = s_b1[j];
#pragma unroll
        for (int k = 0; k < 64; k++) acc += hv[k] * s_w1[k * 32 + j];
        t[j] = acc;
        sum += acc;
    }
    float mean = sum * (1.0f / 32.0f);
    float sq = 0.0f;
#pragma unroll
    for (int j = 0; j < 32; j++) {
        float d = t[j] - mean;
        sq += d * d;
    }
    float inv = rsqrtf(sq * (1.0f / 32.0f) + EPS);
#pragma unroll
    for (int j = 0; j < 32; j++) {
        float y = (t[j] - mean) * inv * s_g4[j] + s_be4[j];
        t[j] = (y > 0.0f) ? y : expm1f(y);
    }
#pragma unroll
    for (int j = 0; j < 32; j++) {
        float acc = s_b2[j];
#pragma unroll
        for (int k = 0; k < 32; k++) acc += t[k] * s_w2[k * 32 + j];
        out[(size_t)n * 32 + j] = acc;
    }
}

// ---------------------------------------------------------------------
extern "C" void kernel_launch(void* const* d_in, const int* in_sizes, int n_in,
                              void* d_out, int out_size) {
    const float* x  = (const float*)d_in[0];
    const void*  ei = d_in[1];
    const float* W1 = (const float*)d_in[2];
    const float* b1 = (const float*)d_in[3];
    const float* g1 = (const float*)d_in[4];
    const float* be1 = (const float*)d_in[5];
    const float* W2 = (const float*)d_in[6];
    const float* b2 = (const float*)d_in[7];
    const float* g2 = (const float*)d_in[8];
    const float* be2 = (const float*)d_in[9];
    const float* W3 = (const float*)d_in[10];
    const float* b3 = (const float*)d_in[11];
    const float* g3 = (const float*)d_in[12];
    const float* be3 = (const float*)d_in[13];
    const float* lw1 = (const float*)d_in[14];
    const float* lb1 = (const float*)d_in[15];
    const float* g4 = (const float*)d_in[16];
    const float* be4 = (const float*)d_in[17];
    const float* lw2 = (const float*)d_in[18];
    const float* lb2 = (const float*)d_in[19];
    float* out = (float*)d_out;

    const int N = NN;
    const int E = in_sizes[1] / 2;

    void* p;
    cudaGetSymbolAddress(&p, g_bufA); float* bufA = (float*)p;
    cudaGetSymbolAddress(&p, g_bufB); float* bufB = (float*)p;
    cudaGetSymbolAddress(&p, g_bufC); float* bufC = (float*)p;

    // graph prep (recomputed every launch, deterministic)
    detect_dtype_kernel<<<1, 256>>>(ei, E, N);
    zero_deg_kernel<<<(N + 255) / 256, 256>>>(N);
    prep_edges_kernel<<<(E + 255) / 256, 256>>>(ei, E);
    dinv_kernel<<<(N + 255) / 256, 256>>>(N);
    norm_kernel<<<(E + 255) / 256, 256>>>(E);

    // ---- layer 1: 128 -> 64 ----
    gemm_kernel<128, 64, 8><<<(N + 31) / 32, 256>>>(x, W1, bufB, N);
    self_init_kernel<64><<<(N * 64 + 255) / 256, 256>>>(bufB, b1, bufC, N);
    {
        long long tot = (long long)E * 16;
        edge_scatter_kernel<4><<<(unsigned)((tot + 255) / 256), 256>>>(bufB, bufC, E);
    }
    ln_elu_kernel<64><<<(N + 7) / 8, 256>>>(bufC, g1, be1, bufA, N);

    // ---- layer 2: 64 -> 128 ----
    gemm_kernel<64, 128, 8><<<(N + 15) / 16, 256>>>(bufA, W2, bufB, N);
    self_init_kernel<128><<<(N * 128 + 255) / 256, 256>>>(bufB, b2, bufC, N);
    {
        long long tot = (long long)E * 32;
        edge_scatter_kernel<5><<<(unsigned)((tot + 255) / 256), 256>>>(bufB, bufC, E);
    }
    ln_elu_kernel<128><<<(N + 7) / 8, 256>>>(bufC, g2, be2, bufA, N);

    // ---- layer 3: 128 -> 64 ----
    gemm_kernel<128, 64, 8><<<(N + 31) / 32, 256>>>(bufA, W3, bufB, N);
    self_init_kernel<64><<<(N * 64 + 255) / 256, 256>>>(bufB, b3, bufC, N);
    {
        long long tot = (long long)E * 16;
        edge_scatter_kernel<4><<<(unsigned)((tot + 255) / 256), 256>>>(bufB, bufC, E);
    }
    ln_elu_kernel<64><<<(N + 7) / 8, 256>>>(bufC, g3, be3, bufA, N);

    // ---- head ----
    head_kernel<<<(N + 127) / 128, 128>>>(bufA, lw1, lb1, g4, be4, lw2, lb2, out, N);
}

// round 3
// speedup vs baseline: 1.3846x; 1.3846x over previous
#include <cuda_runtime.h>
#include <cstdint>

#define NN 100000
#define EMAX 1600000
#define EPS 1e-5f
#define SCAN_CHUNK 256
#define NBLK ((NN + SCAN_CHUNK - 1) / SCAN_CHUNK)   // 391

// ---- scratch (static __device__ globals; no allocation at runtime) ----
__device__ __align__(16) float g_bufA[(size_t)NN * 128];
__device__ __align__(16) float g_bufB[(size_t)NN * 128];
__device__ float g_dinv[NN];
__device__ int   g_deg[NN];
__device__ int   g_off[NN];
__device__ int   g_cur[NN];
__device__ int   g_src[EMAX];
__device__ int   g_dst[EMAX];
__device__ int   g_csr_src[EMAX];
__device__ float g_csr_norm[EMAX];
__device__ int   g_bsum[512];
__device__ int   g_boff[512];
__device__ int   g_is64;

// ---------------------------------------------------------------------
// Detect int64 vs int32 edge_index (JAX w/o x64 silently emits int32).
__global__ void detect_dtype_kernel(const void* ei_raw, int E, int n_nodes) {
    if (threadIdx.x == 0) g_is64 = 1;
    __syncthreads();
    const long long* e64 = (const long long*)ei_raw;
    int cnt = (2 * E < 1024) ? 2 * E : 1024;
    for (int i = threadIdx.x; i < cnt; i += blockDim.x) {
        long long v = e64[i];
        if (v < 0 || v >= n_nodes) atomicExch(&g_is64, 0);
    }
}

__global__ void zero_deg_kernel(int n) {
    int i = blockIdx.x * blockDim.x + threadIdx.x;
    if (i < n) g_deg[i] = 0;
}

__global__ void prep_edges_kernel(const void* ei_raw, int E) {
    int e = blockIdx.x * blockDim.x + threadIdx.x;
    if (e >= E) return;
    int s, d;
    if (g_is64) {
        const long long* ei = (const long long*)ei_raw;
        s = (int)ei[e];
        d = (int)ei[(size_t)E + e];
    } else {
        const int* ei = (const int*)ei_raw;
        s = ei[e];
        d = ei[(size_t)E + e];
    }
    g_src[e] = s;
    g_dst[e] = d;
    atomicAdd(&g_deg[d], 1);
}

// ---- 3-kernel exclusive scan of g_deg -> g_off -----------------------
__global__ void scan_block_sum_kernel(int n) {
    __shared__ int sh[SCAN_CHUNK];
    int i = blockIdx.x * SCAN_CHUNK + threadIdx.x;
    sh[threadIdx.x] = (i < n) ? g_deg[i] : 0;
    __syncthreads();
    for (int s = SCAN_CHUNK / 2; s; s >>= 1) {
        if (threadIdx.x < s) sh[threadIdx.x] += sh[threadIdx.x + s];
        __syncthreads();
    }
    if (threadIdx.x == 0) g_bsum[blockIdx.x] = sh[0];
}

__global__ void scan_boff_kernel(int nb) {
    __shared__ int sh[512];
    int v = (threadIdx.x < nb) ? g_bsum[threadIdx.x] : 0;
    sh[threadIdx.x] = v;
    __syncthreads();
    for (int o = 1; o < 512; o <<= 1) {
        int t = (threadIdx.x >= o) ? sh[threadIdx.x - o] : 0;
        __syncthreads();
        sh[threadIdx.x] += t;
        __syncthreads();
    }
    if (threadIdx.x < nb) g_boff[threadIdx.x] = sh[threadIdx.x] - v;
}

__global__ void scan_final_kernel(int n) {
    __shared__ int sh[SCAN_CHUNK];
    int i = blockIdx.x * SCAN_CHUNK + threadIdx.x;
    int v = (i < n) ? g_deg[i] : 0;
    sh[threadIdx.x] = v;
    __syncthreads();
    for (int o = 1; o < SCAN_CHUNK; o <<= 1) {
        int t = (threadIdx.x >= o) ? sh[threadIdx.x - o] : 0;
        __syncthreads();
        sh[threadIdx.x] += t;
        __syncthreads();
    }
    if (i < n) {
        int off = g_boff[blockIdx.x] + sh[threadIdx.x] - v;
        g_off[i] = off;
        g_cur[i] = off;
        g_dinv[i] = rsqrtf((float)v + 1.0f);   // fused dinv
    }
}

__global__ void fill_csr_kernel(int E) {
    int e = blockIdx.x * blockDim.x + threadIdx.x;
    if (e >= E) return;
    int s = g_src[e];
    int d = g_dst[e];
    int pos = atomicAdd(&g_cur[d], 1);
    g_csr_src[pos] = s;
    g_csr_norm[pos] = g_dinv[s] * g_dinv[d];
}

// ---- GEMM: C[N,Fo] = H[N,Fi] @ W[Fi,Fo], W staged in shared ----------
template <int Fi, int Fo, int NPT>
__global__ void gemm_kernel(const float* __restrict__ H,
                            const float* __restrict__ W,
                            float* __restrict__ C, int N) {
    constexpr int NR = 256 / Fo;
    __shared__ float Ws[Fi * Fo];
    for (int i = threadIdx.x; i < Fi * Fo; i += 256) Ws[i] = W[i];
    __syncthreads();

    int fo = threadIdx.x % Fo;
    int nr = threadIdx.x / Fo;
    int n0 = blockIdx.x * (NR * NPT) + nr * NPT;

    float acc[NPT];
#pragma unroll
    for (int r = 0; r < NPT; r++) acc[r] = 0.0f;

#pragma unroll 4
    for (int k = 0; k < Fi; k++) {
        float w = Ws[k * Fo + fo];
#pragma unroll
        for (int r = 0; r < NPT; r++) {
            int n = n0 + r;
            if (n < N) acc[r] += H[(size_t)n * Fi + k] * w;
        }
    }
#pragma unroll
    for (int r = 0; r < NPT; r++) {
        int n = n0 + r;
        if (n < N) C[(size_t)n * Fo + fo] = acc[r];
    }
}

// ---- fused CSR aggregation + self-loop + bias + LayerNorm + ELU ------
// One G-thread group per destination node, G = F/4, register accumulators.
template <int F>
__global__ void agg_ln_elu_kernel(const float* __restrict__ xw,
                                  const float* __restrict__ bias,
                                  const float* __restrict__ gam,
                                  const float* __restrict__ bet,
                                  float* __restrict__ out, int N) {
    constexpr int G = F / 4;            // threads per node (16 or 32)
    int gid = (int)((blockIdx.x * blockDim.x + threadIdx.x) / G);
    int c = threadIdx.x % G;
    if (gid >= N) return;

    const float4* xw4 = reinterpret_cast<const float4*>(xw);
    float di = g_dinv[gid];
    float sl = di * di;
    float4 a = __ldg(&xw4[(size_t)gid * G + c]);
    float4 acc = make_float4(a.x * sl, a.y * sl, a.z * sl, a.w * sl);

    int off = g_off[gid];
    int deg = g_deg[gid];
#pragma unroll 2
    for (int j = 0; j < deg; j++) {
        int s = __ldg(&g_csr_src[off + j]);
        float w = __ldg(&g_csr_norm[off + j]);
        float4 v = __ldg(&xw4[(size_t)s * G + c]);
        acc.x += v.x * w;
        acc.y += v.y * w;
        acc.z += v.z * w;
        acc.w += v.w * w;
    }

    float4 bb = __ldg(&reinterpret_cast<const float4*>(bias)[c]);
    acc.x += bb.x; acc.y += bb.y; acc.z += bb.z; acc.w += bb.w;

    // LayerNorm across the G-lane group (each lane holds 4 values)
    float sum = acc.x + acc.y + acc.z + acc.w;
    float sq  = acc.x * acc.x + acc.y * acc.y + acc.z * acc.z + acc.w * acc.w;
#pragma unroll
    for (int o = G / 2; o; o >>= 1) {
        sum += __shfl_xor_sync(0xffffffffu, sum, o);
        sq  += __shfl_xor_sync(0xffffffffu, sq, o);
    }
    float mean = sum * (1.0f / F);
    float var  = sq * (1.0f / F) - mean * mean;
    float inv  = rsqrtf(var + EPS);

    float4 gg = __ldg(&reinterpret_cast<const float4*>(gam)[c]);
    float4 be = __ldg(&reinterpret_cast<const float4*>(bet)[c]);
    float4 y;
    y.x = (acc.x - mean) * inv * gg.x + be.x;
    y.y = (acc.y - mean) * inv * gg.y + be.y;
    y.z = (acc.z - mean) * inv * gg.z + be.z;
    y.w = (acc.w - mean) * inv * gg.w + be.w;
    y.x = (y.x > 0.0f) ? y.x : expm1f(y.x);
    y.y = (y.y > 0.0f) ? y.y : expm1f(y.y);
    y.z = (y.z > 0.0f) ? y.z : expm1f(y.z);
    y.w = (y.w > 0.0f) ? y.w : expm1f(y.w);
    reinterpret_cast<float4*>(out)[(size_t)gid * G + c] = y;
}

// ---- fused head: lin(64->32) + LN + ELU + lin(32->32), thread/node ---
__global__ void head_kernel(const float* __restrict__ h,
                            const float* __restrict__ lw1,
                            const float* __restrict__ lb1,
                            const float* __restrict__ g4,
                            const float* __restrict__ be4,
                            const float* __restrict__ lw2,
                            const float* __restrict__ lb2,
                            float* __restrict__ out, int N) {
    __shared__ float s_w1[64 * 32];
    __shared__ float s_w2[32 * 32];
    __shared__ float s_b1[32], s_g4[32], s_be4[32], s_b2[32];
    for (int i = threadIdx.x; i < 64 * 32; i += blockDim.x) s_w1[i] = lw1[i];
    for (int i = threadIdx.x; i < 32 * 32; i += blockDim.x) s_w2[i] = lw2[i];
    if (threadIdx.x < 32) {
        s_b1[threadIdx.x]  = lb1[threadIdx.x];
        s_g4[threadIdx.x]  = g4[threadIdx.x];
        s_be4[threadIdx.x] = be4[threadIdx.x];
        s_b2[threadIdx.x]  = lb2[threadIdx.x];
    }
    __syncthreads();

    int n = blockIdx.x * blockDim.x + threadIdx.x;
    if (n >= N) return;

    float hv[64];
#pragma unroll
    for (int k = 0; k < 64; k++) hv[k] = h[(size_t)n * 64 + k];

    float t[32];
    float sum = 0.0f;
#pragma unroll
    for (int j = 0; j < 32; j++) {
        float acc = s_b1[j];
#pragma unroll
        for (int k = 0; k < 64; k++) acc += hv[k] * s_w1[k * 32 + j];
        t[j] = acc;
        sum += acc;
    }
    float mean = sum * (1.0f / 32.0f);
    float sq = 0.0f;
#pragma unroll
    for (int j = 0; j < 32; j++) {
        float d = t[j] - mean;
        sq += d * d;
    }
    float inv = rsqrtf(sq * (1.0f / 32.0f) + EPS);
#pragma unroll
    for (int j = 0; j < 32; j++) {
        float y = (t[j] - mean) * inv * s_g4[j] + s_be4[j];
        t[j] = (y > 0.0f) ? y : expm1f(y);
    }
#pragma unroll
    for (int j = 0; j < 32; j++) {
        float acc = s_b2[j];
#pragma unroll
        for (int k = 0; k < 32; k++) acc += t[k] * s_w2[k * 32 + j];
        out[(size_t)n * 32 + j] = acc;
    }
}

// ---------------------------------------------------------------------
extern "C" void kernel_launch(void* const* d_in, const int* in_sizes, int n_in,
                              void* d_out, int out_size) {
    const float* x  = (const float*)d_in[0];
    const void*  ei = d_in[1];
    const float* W1 = (const float*)d_in[2];
    const float* b1 = (const float*)d_in[3];
    const float* g1 = (const float*)d_in[4];
    const float* be1 = (const float*)d_in[5];
    const float* W2 = (const float*)d_in[6];
    const float* b2 = (const float*)d_in[7];
    const float* g2 = (const float*)d_in[8];
    const float* be2 = (const float*)d_in[9];
    const float* W3 = (const float*)d_in[10];
    const float* b3 = (const float*)d_in[11];
    const float* g3 = (const float*)d_in[12];
    const float* be3 = (const float*)d_in[13];
    const float* lw1 = (const float*)d_in[14];
    const float* lb1 = (const float*)d_in[15];
    const float* g4 = (const float*)d_in[16];
    const float* be4 = (const float*)d_in[17];
    const float* lw2 = (const float*)d_in[18];
    const float* lb2 = (const float*)d_in[19];
    float* out = (float*)d_out;

    const int N = NN;
    const int E = in_sizes[1] / 2;

    void* p;
    cudaGetSymbolAddress(&p, g_bufA); float* bufA = (float*)p;
    cudaGetSymbolAddress(&p, g_bufB); float* bufB = (float*)p;

    // ---- graph prep: CSR build (recomputed every launch) ----
    detect_dtype_kernel<<<1, 256>>>(ei, E, N);
    zero_deg_kernel<<<(N + 255) / 256, 256>>>(N);
    prep_edges_kernel<<<(E + 255) / 256, 256>>>(ei, E);
    scan_block_sum_kernel<<<NBLK, SCAN_CHUNK>>>(N);
    scan_boff_kernel<<<1, 512>>>(NBLK);
    scan_final_kernel<<<NBLK, SCAN_CHUNK>>>(N);
    fill_csr_kernel<<<(E + 255) / 256, 256>>>(E);

    // ---- layer 1: 128 -> 64 ----
    gemm_kernel<128, 64, 8><<<(N + 31) / 32, 256>>>(x, W1, bufB, N);
    agg_ln_elu_kernel<64><<<(N * 16 + 255) / 256, 256>>>(bufB, b1, g1, be1, bufA, N);

    // ---- layer 2: 64 -> 128 ----
    gemm_kernel<64, 128, 8><<<(N + 15) / 16, 256>>>(bufA, W2, bufB, N);
    agg_ln_elu_kernel<128><<<(N * 32 + 255) / 256, 256>>>(bufB, b2, g2, be2, bufA, N);

    // ---- layer 3: 128 -> 64 ----
    gemm_kernel<128, 64, 8><<<(N + 31) / 32, 256>>>(bufA, W3, bufB, N);
    agg_ln_elu_kernel<64><<<(N * 16 + 255) / 256, 256>>>(bufB, b3, g3, be3, bufA, N);

    // ---- head ----
    head_kernel<<<(N + 127) / 128, 128>>>(bufA, lw1, lb1, g4, be4, lw2, lb2, out, N);
}

// round 4
// speedup vs baseline: 1.5999x; 1.1554x over previous
#include <cuda_runtime.h>
#include <cstdint>

#define NN 100000
#define EMAX 1600000
#define EPS 1e-5f
#define SCAN_CHUNK 256
#define NBLK ((NN + SCAN_CHUNK - 1) / SCAN_CHUNK)   // 391

// ---- scratch (static __device__ globals; no allocation at runtime) ----
__device__ __align__(16) float g_bufA[(size_t)NN * 128];
__device__ __align__(16) float g_bufB[(size_t)NN * 128];
__device__ float g_dinv[NN];
__device__ int   g_deg[NN];
__device__ int   g_off[NN];
__device__ int   g_cur[NN];
__device__ int   g_src[EMAX];
__device__ int   g_dst[EMAX];
__device__ __align__(8) int2 g_csr[EMAX];   // {src, bitcast(norm)}
__device__ int   g_bsum[512];
__device__ int   g_boff[512];
__device__ int   g_is64;

// ---------------------------------------------------------------------
// Detect int64 vs int32 edge_index (JAX w/o x64 silently emits int32).
__global__ void detect_dtype_kernel(const void* ei_raw, int E, int n_nodes) {
    if (threadIdx.x == 0) g_is64 = 1;
    __syncthreads();
    const long long* e64 = (const long long*)ei_raw;
    int cnt = (2 * E < 1024) ? 2 * E : 1024;
    for (int i = threadIdx.x; i < cnt; i += blockDim.x) {
        long long v = e64[i];
        if (v < 0 || v >= n_nodes) atomicExch(&g_is64, 0);
    }
}

__global__ void zero_deg_kernel(int n) {
    int i = blockIdx.x * blockDim.x + threadIdx.x;
    if (i < n) g_deg[i] = 0;
}

// 4 edges per thread, vectorized int4 path for int32 input
__global__ void prep_edges_kernel(const void* ei_raw, int E) {
    int t = blockIdx.x * blockDim.x + threadIdx.x;
    int e0 = t * 4;
    if (e0 >= E) return;
    int s[4], d[4];
    int cnt = (E - e0 < 4) ? (E - e0) : 4;
    if (g_is64) {
        const long long* ei = (const long long*)ei_raw;
        for (int i = 0; i < cnt; i++) {
            s[i] = (int)ei[e0 + i];
            d[i] = (int)ei[(size_t)E + e0 + i];
        }
    } else {
        const int* ei = (const int*)ei_raw;
        if (cnt == 4 && (e0 % 4) == 0 && (E % 4) == 0) {
            int4 sv = __ldg(&reinterpret_cast<const int4*>(ei)[t]);
            int4 dv = __ldg(&reinterpret_cast<const int4*>(ei + E)[t]);
            s[0] = sv.x; s[1] = sv.y; s[2] = sv.z; s[3] = sv.w;
            d[0] = dv.x; d[1] = dv.y; d[2] = dv.z; d[3] = dv.w;
        } else {
            for (int i = 0; i < cnt; i++) {
                s[i] = ei[e0 + i];
                d[i] = ei[(size_t)E + e0 + i];
            }
        }
    }
    for (int i = 0; i < cnt; i++) {
        g_src[e0 + i] = s[i];
        g_dst[e0 + i] = d[i];
        atomicAdd(&g_deg[d[i]], 1);
    }
}

// ---- 3-kernel exclusive scan of g_deg -> g_off -----------------------
__global__ void scan_block_sum_kernel(int n) {
    __shared__ int sh[SCAN_CHUNK];
    int i = blockIdx.x * SCAN_CHUNK + threadIdx.x;
    sh[threadIdx.x] = (i < n) ? g_deg[i] : 0;
    __syncthreads();
    for (int s = SCAN_CHUNK / 2; s; s >>= 1) {
        if (threadIdx.x < s) sh[threadIdx.x] += sh[threadIdx.x + s];
        __syncthreads();
    }
    if (threadIdx.x == 0) g_bsum[blockIdx.x] = sh[0];
}

__global__ void scan_boff_kernel(int nb) {
    __shared__ int sh[512];
    int v = (threadIdx.x < nb) ? g_bsum[threadIdx.x] : 0;
    sh[threadIdx.x] = v;
    __syncthreads();
    for (int o = 1; o < 512; o <<= 1) {
        int t = (threadIdx.x >= o) ? sh[threadIdx.x - o] : 0;
        __syncthreads();
        sh[threadIdx.x] += t;
        __syncthreads();
    }
    if (threadIdx.x < nb) g_boff[threadIdx.x] = sh[threadIdx.x] - v;
}

__global__ void scan_final_kernel(int n) {
    __shared__ int sh[SCAN_CHUNK];
    int i = blockIdx.x * SCAN_CHUNK + threadIdx.x;
    int v = (i < n) ? g_deg[i] : 0;
    sh[threadIdx.x] = v;
    __syncthreads();
    for (int o = 1; o < SCAN_CHUNK; o <<= 1) {
        int t = (threadIdx.x >= o) ? sh[threadIdx.x - o] : 0;
        __syncthreads();
        sh[threadIdx.x] += t;
        __syncthreads();
    }
    if (i < n) {
        int off = g_boff[blockIdx.x] + sh[threadIdx.x] - v;
        g_off[i] = off;
        g_cur[i] = off;
        g_dinv[i] = rsqrtf((float)v + 1.0f);   // fused dinv
    }
}

__global__ void fill_csr_kernel(int E) {
    int e = blockIdx.x * blockDim.x + threadIdx.x;
    if (e >= E) return;
    int s = g_src[e];
    int d = g_dst[e];
    int pos = atomicAdd(&g_cur[d], 1);
    float nrm = g_dinv[s] * g_dinv[d];
    g_csr[pos] = make_int2(s, __float_as_int(nrm));
}

// ---- GEMM: C[N,Fo] = H[N,Fi] @ W[Fi,Fo] (+bias), float4 H loads ------
template <int Fi, int Fo, int NPT>
__global__ void gemm_kernel(const float* __restrict__ H,
                            const float* __restrict__ W,
                            const float* __restrict__ bias,
                            float* __restrict__ C, int N) {
    constexpr int NR = 256 / Fo;
    __shared__ float Ws[Fi * Fo];
    for (int i = threadIdx.x; i < Fi * Fo; i += 256) Ws[i] = W[i];
    __syncthreads();

    int fo = threadIdx.x % Fo;
    int nr = threadIdx.x / Fo;
    int n0 = blockIdx.x * (NR * NPT) + nr * NPT;

    float acc[NPT];
#pragma unroll
    for (int r = 0; r < NPT; r++) acc[r] = 0.0f;

    const float4* H4 = reinterpret_cast<const float4*>(H);
#pragma unroll 2
    for (int k4 = 0; k4 < Fi / 4; k4++) {
        float w0 = Ws[(k4 * 4 + 0) * Fo + fo];
        float w1 = Ws[(k4 * 4 + 1) * Fo + fo];
        float w2 = Ws[(k4 * 4 + 2) * Fo + fo];
        float w3 = Ws[(k4 * 4 + 3) * Fo + fo];
#pragma unroll
        for (int r = 0; r < NPT; r++) {
            int n = n0 + r;
            if (n < N) {
                float4 h = __ldg(&H4[(size_t)n * (Fi / 4) + k4]);
                acc[r] += h.x * w0 + h.y * w1 + h.z * w2 + h.w * w3;
            }
        }
    }
    float bb = bias ? bias[fo] : 0.0f;
#pragma unroll
    for (int r = 0; r < NPT; r++) {
        int n = n0 + r;
        if (n < N) C[(size_t)n * Fo + fo] = acc[r] + bb;
    }
}

// ---- plain CSR aggregation (self-loop, no bias/LN): out = A_hat @ h --
template <int F>
__global__ void agg_kernel(const float* __restrict__ h,
                           float* __restrict__ out, int N) {
    constexpr int G = F / 4;
    int gid = (int)((blockIdx.x * blockDim.x + threadIdx.x) / G);
    int c = threadIdx.x % G;
    if (gid >= N) return;

    const float4* h4 = reinterpret_cast<const float4*>(h);
    float di = g_dinv[gid];
    float sl = di * di;
    float4 a = __ldg(&h4[(size_t)gid * G + c]);
    float4 acc = make_float4(a.x * sl, a.y * sl, a.z * sl, a.w * sl);

    int off = g_off[gid];
    int deg = g_deg[gid];
#pragma unroll 2
    for (int j = 0; j < deg; j++) {
        int2 sn = __ldg(&g_csr[off + j]);
        float w = __int_as_float(sn.y);
        float4 v = __ldg(&h4[(size_t)sn.x * G + c]);
        acc.x += v.x * w;
        acc.y += v.y * w;
        acc.z += v.z * w;
        acc.w += v.w * w;
    }
    reinterpret_cast<float4*>(out)[(size_t)gid * G + c] = acc;
}

// ---- fused CSR aggregation + self-loop + bias + LayerNorm + ELU ------
template <int F>
__global__ void agg_ln_elu_kernel(const float* __restrict__ xw,
                                  const float* __restrict__ bias,
                                  const float* __restrict__ gam,
                                  const float* __restrict__ bet,
                                  float* __restrict__ out, int N) {
    constexpr int G = F / 4;
    int gid = (int)((blockIdx.x * blockDim.x + threadIdx.x) / G);
    int c = threadIdx.x % G;
    if (gid >= N) return;

    const float4* xw4 = reinterpret_cast<const float4*>(xw);
    float di = g_dinv[gid];
    float sl = di * di;
    float4 a = __ldg(&xw4[(size_t)gid * G + c]);
    float4 acc = make_float4(a.x * sl, a.y * sl, a.z * sl, a.w * sl);

    int off = g_off[gid];
    int deg = g_deg[gid];
#pragma unroll 2
    for (int j = 0; j < deg; j++) {
        int2 sn = __ldg(&g_csr[off + j]);
        float w = __int_as_float(sn.y);
        float4 v = __ldg(&xw4[(size_t)sn.x * G + c]);
        acc.x += v.x * w;
        acc.y += v.y * w;
        acc.z += v.z * w;
        acc.w += v.w * w;
    }

    float4 bb = __ldg(&reinterpret_cast<const float4*>(bias)[c]);
    acc.x += bb.x; acc.y += bb.y; acc.z += bb.z; acc.w += bb.w;

    float sum = acc.x + acc.y + acc.z + acc.w;
    float sq  = acc.x * acc.x + acc.y * acc.y + acc.z * acc.z + acc.w * acc.w;
#pragma unroll
    for (int o = G / 2; o; o >>= 1) {
        sum += __shfl_xor_sync(0xffffffffu, sum, o);
        sq  += __shfl_xor_sync(0xffffffffu, sq, o);
    }
    float mean = sum * (1.0f / F);
    float var  = sq * (1.0f / F) - mean * mean;
    float inv  = rsqrtf(var + EPS);

    float4 gg = __ldg(&reinterpret_cast<const float4*>(gam)[c]);
    float4 be = __ldg(&reinterpret_cast<const float4*>(bet)[c]);
    float4 y;
    y.x = (acc.x - mean) * inv * gg.x + be.x;
    y.y = (acc.y - mean) * inv * gg.y + be.y;
    y.z = (acc.z - mean) * inv * gg.z + be.z;
    y.w = (acc.w - mean) * inv * gg.w + be.w;
    y.x = (y.x > 0.0f) ? y.x : expm1f(y.x);
    y.y = (y.y > 0.0f) ? y.y : expm1f(y.y);
    y.z = (y.z > 0.0f) ? y.z : expm1f(y.z);
    y.w = (y.w > 0.0f) ? y.w : expm1f(y.w);
    reinterpret_cast<float4*>(out)[(size_t)gid * G + c] = y;
}

// ---- standalone LayerNorm + ELU (layer 2 post-GEMM), warp per node ---
template <int Fo>
__global__ void ln_elu_kernel(const float* __restrict__ in,
                              const float* __restrict__ g,
                              const float* __restrict__ be,
                              float* __restrict__ out, int N) {
    constexpr int VPL = Fo / 32;
    int warp = (int)((blockIdx.x * blockDim.x + threadIdx.x) >> 5);
    int lane = threadIdx.x & 31;
    if (warp >= N) return;
    float v[VPL];
    float sum = 0.0f, sq = 0.0f;
#pragma unroll
    for (int i = 0; i < VPL; i++) {
        v[i] = in[(size_t)warp * Fo + lane + i * 32];
        sum += v[i];
        sq += v[i] * v[i];
    }
#pragma unroll
    for (int o = 16; o; o >>= 1) {
        sum += __shfl_xor_sync(0xffffffffu, sum, o);
        sq  += __shfl_xor_sync(0xffffffffu, sq, o);
    }
    float mean = sum * (1.0f / Fo);
    float var  = sq * (1.0f / Fo) - mean * mean;
    float inv  = rsqrtf(var + EPS);
#pragma unroll
    for (int i = 0; i < VPL; i++) {
        int f = lane + i * 32;
        float y = (v[i] - mean) * inv * g[f] + be[f];
        out[(size_t)warp * Fo + f] = (y > 0.0f) ? y : expm1f(y);
    }
}

// ---- fused head: lin(64->32) + LN + ELU + lin(32->32), thread/node ---
__global__ void head_kernel(const float* __restrict__ h,
                            const float* __restrict__ lw1,
                            const float* __restrict__ lb1,
                            const float* __restrict__ g4,
                            const float* __restrict__ be4,
                            const float* __restrict__ lw2,
                            const float* __restrict__ lb2,
                            float* __restrict__ out, int N) {
    __shared__ float s_w1[64 * 32];
    __shared__ float s_w2[32 * 32];
    __shared__ float s_b1[32], s_g4[32], s_be4[32], s_b2[32];
    for (int i = threadIdx.x; i < 64 * 32; i += blockDim.x) s_w1[i] = lw1[i];
    for (int i = threadIdx.x; i < 32 * 32; i += blockDim.x) s_w2[i] = lw2[i];
    if (threadIdx.x < 32) {
        s_b1[threadIdx.x]  = lb1[threadIdx.x];
        s_g4[threadIdx.x]  = g4[threadIdx.x];
        s_be4[threadIdx.x] = be4[threadIdx.x];
        s_b2[threadIdx.x]  = lb2[threadIdx.x];
    }
    __syncthreads();

    int n = blockIdx.x * blockDim.x + threadIdx.x;
    if (n >= N) return;

    float hv[64];
#pragma unroll
    for (int k = 0; k < 64; k++) hv[k] = h[(size_t)n * 64 + k];

    float t[32];
    float sum = 0.0f;
#pragma unroll
    for (int j = 0; j < 32; j++) {
        float acc = s_b1[j];
#pragma unroll
        for (int k = 0; k < 64; k++) acc += hv[k] * s_w1[k * 32 + j];
        t[j] = acc;
        sum += acc;
    }
    float mean = sum * (1.0f / 32.0f);
    float sq = 0.0f;
#pragma unroll
    for (int j = 0; j < 32; j++) {
        float d = t[j] - mean;
        sq += d * d;
    }
    float inv = rsqrtf(sq * (1.0f / 32.0f) + EPS);
#pragma unroll
    for (int j = 0; j < 32; j++) {
        float y = (t[j] - mean) * inv * s_g4[j] + s_be4[j];
        t[j] = (y > 0.0f) ? y : expm1f(y);
    }
#pragma unroll
    for (int j = 0; j < 32; j++) {
        float acc = s_b2[j];
#pragma unroll
        for (int k = 0; k < 32; k++) acc += t[k] * s_w2[k * 32 + j];
        out[(size_t)n * 32 + j] = acc;
    }
}

// ---------------------------------------------------------------------
extern "C" void kernel_launch(void* const* d_in, const int* in_sizes, int n_in,
                              void* d_out, int out_size) {
    const float* x  = (const float*)d_in[0];
    const void*  ei = d_in[1];
    const float* W1 = (const float*)d_in[2];
    const float* b1 = (const float*)d_in[3];
    const float* g1 = (const float*)d_in[4];
    const float* be1 = (const float*)d_in[5];
    const float* W2 = (const float*)d_in[6];
    const float* b2 = (const float*)d_in[7];
    const float* g2 = (const float*)d_in[8];
    const float* be2 = (const float*)d_in[9];
    const float* W3 = (const float*)d_in[10];
    const float* b3 = (const float*)d_in[11];
    const float* g3 = (const float*)d_in[12];
    const float* be3 = (const float*)d_in[13];
    const float* lw1 = (const float*)d_in[14];
    const float* lb1 = (const float*)d_in[15];
    const float* g4 = (const float*)d_in[16];
    const float* be4 = (const float*)d_in[17];
    const float* lw2 = (const float*)d_in[18];
    const float* lb2 = (const float*)d_in[19];
    float* out = (float*)d_out;

    const int N = NN;
    const int E = in_sizes[1] / 2;

    void* p;
    cudaGetSymbolAddress(&p, g_bufA); float* bufA = (float*)p;
    cudaGetSymbolAddress(&p, g_bufB); float* bufB = (float*)p;

    // ---- graph prep: CSR build (recomputed every launch) ----
    detect_dtype_kernel<<<1, 256>>>(ei, E, N);
    zero_deg_kernel<<<(N + 255) / 256, 256>>>(N);
    prep_edges_kernel<<<(E / 4 + 255) / 256, 256>>>(ei, E);
    scan_block_sum_kernel<<<NBLK, SCAN_CHUNK>>>(N);
    scan_boff_kernel<<<1, 512>>>(NBLK);
    scan_final_kernel<<<NBLK, SCAN_CHUNK>>>(N);
    fill_csr_kernel<<<(E + 255) / 256, 256>>>(E);

    // ---- layer 1: GEMM(x,W1) 128->64, then agg+bias+LN+ELU ----
    gemm_kernel<128, 64, 8><<<(N + 31) / 32, 256>>>(x, W1, nullptr, bufB, N);
    agg_ln_elu_kernel<64><<<(N * 16 + 255) / 256, 256>>>(bufB, b1, g1, be1, bufA, N);

    // ---- layer 2: agg in 64-dim FIRST (linearity), then GEMM 64->128+b2, LN, ELU ----
    agg_kernel<64><<<(N * 16 + 255) / 256, 256>>>(bufA, bufB, N);
    gemm_kernel<64, 128, 8><<<(N + 15) / 16, 256>>>(bufB, W2, b2, bufA, N);
    ln_elu_kernel<128><<<(N + 7) / 8, 256>>>(bufA, g2, be2, bufB, N);

    // ---- layer 3: GEMM 128->64, then agg+bias+LN+ELU ----
    gemm_kernel<128, 64, 8><<<(N + 31) / 32, 256>>>(bufB, W3, nullptr, bufA, N);
    agg_ln_elu_kernel<64><<<(N * 16 + 255) / 256, 256>>>(bufA, b3, g3, be3, bufB, N);

    // ---- head ----
    head_kernel<<<(N + 127) / 128, 128>>>(bufB, lw1, lb1, g4, be4, lw2, lb2, out, N);
}